// round 15
// baseline (speedup 1.0000x reference)
#include <cuda_runtime.h>
#include <cuda_fp16.h>
#include <mma.h>
#include <math.h>

using namespace nvcuda;

#define NNODES 50000
#define NEDGES 800000
#define INF    128
#define HID    64
#define HEADS  4
#define C1     256   // HEADS*HID
#define NEG    0.2f

// ---------------- scratch (device globals; no runtime allocation) ----------
__device__ __half g_h1h [NNODES * C1];  // layer1 pre-attention features (fp16)
__device__ __half g_h1eh[NNODES * C1];  // layer1 output (post bias+ELU), fp16
__device__ float  g_as1[NNODES * HEADS];
__device__ float  g_ad1[NNODES * HEADS];
__device__ __half g_h2h[NNODES * HID];  // layer2 pre-attention features (fp16)
__device__ float  g_as2[NNODES];
__device__ float  g_ad2[NNODES];
__device__ int    g_deg   [NNODES];
__device__ int    g_rowptr[NNODES + 1];
__device__ int    g_cursor[NNODES];
__device__ int    g_col   [NEDGES];
__device__ int    g_bsum  [64];

__device__ __forceinline__ float lrelu(float v) { return v > 0.f ? v : NEG * v; }

// ---------------- CSR construction ------------------------------------------
__global__ void k_scan1() {
    __shared__ int sh[1024];
    int tid = threadIdx.x;
    int i = blockIdx.x * 1024 + tid;
    int v = (i < NNODES) ? g_deg[i] : 0;
    sh[tid] = v;
    __syncthreads();
    for (int s = 1; s < 1024; s <<= 1) {
        int t = (tid >= s) ? sh[tid - s] : 0;
        __syncthreads();
        sh[tid] += t;
        __syncthreads();
    }
    if (i < NNODES) g_rowptr[i] = sh[tid] - v;
    if (tid == 1023) g_bsum[blockIdx.x] = sh[1023];
}

// apply per-block offset, init cursor, zero g_deg for next replay
__global__ void k_scan23() {
    __shared__ int soff;
    int tid = threadIdx.x;
    int bid = blockIdx.x;
    if (tid < 32) {
        int v = 0;
        if (tid < bid && tid < 49) v += g_bsum[tid];
        int t2 = tid + 32;
        if (t2 < bid && t2 < 49) v += g_bsum[t2];
#pragma unroll
        for (int s = 16; s >= 1; s >>= 1) v += __shfl_xor_sync(0xffffffffu, v, s);
        if (tid == 0) soff = v;
    }
    __syncthreads();
    int i = bid * 1024 + tid;
    if (i < NNODES) {
        int r = g_rowptr[i] + soff;
        g_rowptr[i] = r;
        g_cursor[i] = r;
        g_deg[i] = 0;
    }
    if (i == 0) g_rowptr[NNODES] = NEDGES;
}

__global__ void k_scatter(const int* __restrict__ src, const int* __restrict__ dst) {
    int i = blockIdx.x * blockDim.x + threadIdx.x;
    if (i < NEDGES) {
        int p = atomicAdd(&g_cursor[dst[i]], 1);
        g_col[p] = src[i];
    }
}

// ---------------- layer 1 GEMM via wmma: 64 nodes x 256 ch per block --------
// 512 threads = 16 warps as 2m x 8n; warp tile 32 x 32 (2x2 accum frags).
// FUSED: per-block 1024-edge degree-histogram slice (atomics hide in stalls);
//        W1 fp32->fp16 conversion inline in B staging (no g_w1h pass).
// Single-phase epilogue; attention vectors staged TRANSPOSED (conflict-free).
// smem: mainloop [0,17408) sA | [17408,84992) sB ; epilogue [0,66560) sC
//       [84992,86016) attTs | [86016,87040) attTd
#define SZ1 87040
__global__ void __launch_bounds__(512, 2)
k_gemm1(const float* __restrict__ x, const float* __restrict__ W1,
        const int* __restrict__ dst,
        const float* __restrict__ att_s, const float* __restrict__ att_d) {
    extern __shared__ __align__(16) char smem[];
    __half* sA = (__half*)smem;
    __half* sB = (__half*)(smem + 17408);
    float*  sC = (float*)smem;                 // aliases sA+sB (dead after mainloop)
    float*  attTs = (float*)(smem + 84992);    // attTs[i*32+q] = att_s[q*8+i]
    float*  attTd = (float*)(smem + 86016);
    int t = threadIdx.x;
    int w = t >> 5;
    int wmh = w & 1, wng = w >> 1;             // m-half 0..1, n-group 0..7
    int m0 = blockIdx.x * 64;

    // fused degree histogram: this block's 1024-edge slice (2 edges/thread)
    {
        int e0 = blockIdx.x * 1024;
#pragma unroll
        for (int i = 0; i < 2; i++) {
            int e = e0 + t + i * 512;
            if (e < NEDGES) atomicAdd(&g_deg[dst[e]], 1);
        }
    }

    // stage transposed attention vectors (own region; no aliasing)
    if (t < C1)           attTs[(t & 7) * 32 + (t >> 3)] = att_s[t];
    else if (t < 2 * C1)  { int u = t - C1; attTd[(u & 7) * 32 + (u >> 3)] = att_d[u]; }

    // stage A with fused fp32->fp16: 64 rows x 128 ch
    for (int i = t; i < 1024; i += 512) {
        int r = i >> 4, q = i & 15;
        int n = m0 + r;
        uint4 st = make_uint4(0, 0, 0, 0);
        if (n < NNODES) {
            const float4* xp = (const float4*)(x + (size_t)n * INF + q * 8);
            float4 v0 = xp[0], v1 = xp[1];
            __half2* p = (__half2*)&st;
            p[0] = __floats2half2_rn(v0.x, v0.y);
            p[1] = __floats2half2_rn(v0.z, v0.w);
            p[2] = __floats2half2_rn(v1.x, v1.y);
            p[3] = __floats2half2_rn(v1.z, v1.w);
        }
        *(uint4*)(sA + r * 136 + q * 8) = st;
    }
    // stage B with fused fp32->fp16: all of W1 (128 rows x 256)
    for (int i = t; i < 4096; i += 512) {
        int r = i >> 5, q = i & 31;
        const float4* wp = (const float4*)(W1 + (size_t)r * C1 + q * 8);
        float4 v0 = wp[0], v1 = wp[1];
        uint4 st;
        __half2* p = (__half2*)&st;
        p[0] = __floats2half2_rn(v0.x, v0.y);
        p[1] = __floats2half2_rn(v0.z, v0.w);
        p[2] = __floats2half2_rn(v1.x, v1.y);
        p[3] = __floats2half2_rn(v1.z, v1.w);
        *(uint4*)(sB + r * 264 + q * 8) = st;
    }
    __syncthreads();

    wmma::fragment<wmma::accumulator, 16, 16, 16, float> c[2][2];
#pragma unroll
    for (int i = 0; i < 2; i++)
#pragma unroll
        for (int j = 0; j < 2; j++) wmma::fill_fragment(c[i][j], 0.f);

#pragma unroll
    for (int kk = 0; kk < 8; kk++) {
        wmma::fragment<wmma::matrix_a, 16, 16, 16, __half, wmma::row_major> af[2];
#pragma unroll
        for (int i = 0; i < 2; i++)
            wmma::load_matrix_sync(af[i], sA + (wmh * 2 + i) * 16 * 136 + kk * 16, 136);
#pragma unroll
        for (int j = 0; j < 2; j++) {
            wmma::fragment<wmma::matrix_b, 16, 16, 16, __half, wmma::row_major> bf;
            wmma::load_matrix_sync(bf, sB + kk * 16 * 264 + (wng * 2 + j) * 16, 264);
            wmma::mma_sync(c[0][j], af[0], bf, c[0][j]);
            wmma::mma_sync(c[1][j], af[1], bf, c[1][j]);
        }
    }

    __syncthreads();                 // sA/sB dead; sC live
#pragma unroll
    for (int i = 0; i < 2; i++)
#pragma unroll
        for (int j = 0; j < 2; j++)
            wmma::store_matrix_sync(sC + ((wmh * 2 + i) * 16) * 260 + (wng * 2 + j) * 16,
                                    c[i][j], 260, wmma::mem_row_major);
    __syncthreads();

    // each thread: 4 rows x 8 cols; fp16 store + fused attention dots
    int r0 = t >> 5, q = t & 31, c0 = q * 8;
#pragma unroll
    for (int k = 0; k < 4; k++) {
        int r = r0 + k * 16;
        int n = m0 + r;
        const float* src = sC + r * 260 + c0;
        if (n < NNODES) {
            uint4 st;
            __half2* p = (__half2*)&st;
            p[0] = __floats2half2_rn(src[0], src[1]);
            p[1] = __floats2half2_rn(src[2], src[3]);
            p[2] = __floats2half2_rn(src[4], src[5]);
            p[3] = __floats2half2_rn(src[6], src[7]);
            *(uint4*)(g_h1h + (size_t)n * C1 + c0) = st;
        }
        float ps = 0.f, pd = 0.f;
#pragma unroll
        for (int i = 0; i < 8; i++) {
            float v = src[i];
            ps = fmaf(v, attTs[i * 32 + q], ps);
            pd = fmaf(v, attTd[i * 32 + q], pd);
        }
#pragma unroll
        for (int s = 1; s <= 4; s <<= 1) {
            ps += __shfl_xor_sync(0xffffffffu, ps, s);
            pd += __shfl_xor_sync(0xffffffffu, pd, s);
        }
        if ((q & 7) == 0 && n < NNODES) {
            int h = q >> 3;
            g_as1[n * HEADS + h] = ps;
            g_ad1[n * HEADS + h] = pd;
        }
    }
}

// ---------------- layer 1: warp-per-destination softmax aggregation ---------
// scores |e| <~ 10 so exp() cannot overflow fp32; max-shift unnecessary.
__global__ void k_agg1(const float* __restrict__ b1) {
    int wid = threadIdx.x >> 5, l = threadIdx.x & 31;
    int d = blockIdx.x * 4 + wid;
    if (d >= NNODES) return;
    int h = l >> 3;
    int ch = 8 * l;

    float adst = g_ad1[d * HEADS + h];
    float w = __expf(lrelu(g_as1[d * HEADS + h] + adst));  // self-loop
    float den = w;
    float a[8];
    {
        uint4 raw = *(const uint4*)(g_h1h + (size_t)d * C1 + ch);
        const __half2* hp = (const __half2*)&raw;
#pragma unroll
        for (int i = 0; i < 4; i++) {
            float2 v = __half22float2(hp[i]);
            a[2 * i]     = w * v.x;
            a[2 * i + 1] = w * v.y;
        }
    }

    int beg = g_rowptr[d], end = g_rowptr[d + 1];
#pragma unroll 4
    for (int j = beg; j < end; j++) {
        int s = g_col[j];
        float ww = __expf(lrelu(g_as1[s * HEADS + h] + adst));
        den += ww;
        uint4 raw = *(const uint4*)(g_h1h + (size_t)s * C1 + ch);
        const __half2* hp = (const __half2*)&raw;
#pragma unroll
        for (int i = 0; i < 4; i++) {
            float2 v = __half22float2(hp[i]);
            a[2 * i]     = fmaf(ww, v.x, a[2 * i]);
            a[2 * i + 1] = fmaf(ww, v.y, a[2 * i + 1]);
        }
    }
    float inv = 1.f / den;
    float4 b0 = *(const float4*)(b1 + ch);
    float4 b4 = *(const float4*)(b1 + ch + 4);
    float o[8];
    o[0] = a[0] * inv + b0.x; o[1] = a[1] * inv + b0.y;
    o[2] = a[2] * inv + b0.z; o[3] = a[3] * inv + b0.w;
    o[4] = a[4] * inv + b4.x; o[5] = a[5] * inv + b4.y;
    o[6] = a[6] * inv + b4.z; o[7] = a[7] * inv + b4.w;
#pragma unroll
    for (int i = 0; i < 8; i++) o[i] = o[i] > 0.f ? o[i] : expm1f(o[i]);
    uint4 st;
    __half2* sp = (__half2*)&st;
    sp[0] = __floats2half2_rn(o[0], o[1]);
    sp[1] = __floats2half2_rn(o[2], o[3]);
    sp[2] = __floats2half2_rn(o[4], o[5]);
    sp[3] = __floats2half2_rn(o[6], o[7]);
    *(uint4*)(g_h1eh + (size_t)d * C1 + ch) = st;
}

// ---------------- layer 2 GEMM via wmma: 64 nodes x 64 ch per block ---------
// 512 threads = 16 warps (4m x 4n); warp tile 16 x 16 (1 accum frag).
// W2 fp32->fp16 conversion inline in B staging.
// layout: mainloop [0,33792) sA | [33792,70656) sB
//         epilogue [0,17408) sC | [70656,70912) attTs | [70912,71168) attTd
#define SZ2 71168
__global__ void __launch_bounds__(512, 2)
k_gemm2(const float* __restrict__ W2,
        const float* __restrict__ att_s, const float* __restrict__ att_d) {
    extern __shared__ __align__(16) char smem[];
    __half* sA = (__half*)smem;
    __half* sB = (__half*)(smem + 33792);
    float*  sC = (float*)smem;                 // aliases sA (dead after mainloop)
    float*  attTs = (float*)(smem + 70656);    // attTs[i*32+q] = att_s[q*2+i]
    float*  attTd = (float*)(smem + 70912);
    int t = threadIdx.x;
    int w = t >> 5;
    int wm = w >> 2, wn = w & 3;
    int m0 = blockIdx.x * 64;

    if (t < HID)            attTs[(t & 1) * 32 + (t >> 1)] = att_s[t];
    else if (t < 2 * HID)   { int u = t - HID; attTd[(u & 1) * 32 + (u >> 1)] = att_d[u]; }

    // stage A: 64 rows x 256 fp16
    for (int i = t; i < 2048; i += 512) {
        int r = i >> 5, q = i & 31;
        uint4 v = make_uint4(0, 0, 0, 0);
        if (m0 + r < NNODES) v = *(const uint4*)(g_h1eh + (size_t)(m0 + r) * C1 + q * 8);
        *(uint4*)(sA + r * 264 + q * 8) = v;
    }
    // stage B with fused fp32->fp16: all of W2 (256 rows x 64)
    for (int i = t; i < 2048; i += 512) {
        int r = i >> 3, q = i & 7;
        const float4* wp = (const float4*)(W2 + (size_t)r * HID + q * 8);
        float4 v0 = wp[0], v1 = wp[1];
        uint4 st;
        __half2* p = (__half2*)&st;
        p[0] = __floats2half2_rn(v0.x, v0.y);
        p[1] = __floats2half2_rn(v0.z, v0.w);
        p[2] = __floats2half2_rn(v1.x, v1.y);
        p[3] = __floats2half2_rn(v1.z, v1.w);
        *(uint4*)(sB + r * 72 + q * 8) = st;
    }
    __syncthreads();

    wmma::fragment<wmma::accumulator, 16, 16, 16, float> c;
    wmma::fill_fragment(c, 0.f);

#pragma unroll
    for (int kk = 0; kk < 16; kk++) {
        wmma::fragment<wmma::matrix_a, 16, 16, 16, __half, wmma::row_major> af;
        wmma::load_matrix_sync(af, sA + wm * 16 * 264 + kk * 16, 264);
        wmma::fragment<wmma::matrix_b, 16, 16, 16, __half, wmma::row_major> bf;
        wmma::load_matrix_sync(bf, sB + kk * 16 * 72 + wn * 16, 72);
        wmma::mma_sync(c, af, bf, c);
    }

    __syncthreads();                 // sA/sB dead
    wmma::store_matrix_sync(sC + (wm * 16) * 68 + wn * 16, c, 68, wmma::mem_row_major);
    __syncthreads();

    // each thread: 4 rows x 2 cols
    int r0 = t >> 5, q = t & 31, c0 = q * 2;
#pragma unroll
    for (int k = 0; k < 4; k++) {
        int r = r0 + k * 16;
        int n = m0 + r;
        const float* src = sC + r * 68 + c0;
        if (n < NNODES)
            *(__half2*)(g_h2h + (size_t)n * HID + c0) = __floats2half2_rn(src[0], src[1]);
        float ps = src[0] * attTs[q] + src[1] * attTs[32 + q];
        float pd = src[0] * attTd[q] + src[1] * attTd[32 + q];
#pragma unroll
        for (int s = 1; s <= 16; s <<= 1) {
            ps += __shfl_xor_sync(0xffffffffu, ps, s);
            pd += __shfl_xor_sync(0xffffffffu, pd, s);
        }
        if (q == 0 && n < NNODES) {
            g_as2[n] = ps;
            g_ad2[n] = pd;
        }
    }
}

// ---------------- layer 2 aggregation + bias/ELU + MLP head -----------------
__global__ void k_agg2(const float* __restrict__ b2,
                       const float* __restrict__ Wm1, const float* __restrict__ bm1,
                       const float* __restrict__ Wm2, const float* __restrict__ bm2,
                       float* __restrict__ out) {
    __shared__ float sh[4][HID];
    int wid = threadIdx.x >> 5, l = threadIdx.x & 31;
    int d = blockIdx.x * 4 + wid;
    if (d >= NNODES) return;
    int grp = l >> 3, cl = l & 7;
    int ch = 8 * cl;

    float adst = g_ad2[d];
    float den = 0.f;
    float a[8] = {0.f, 0.f, 0.f, 0.f, 0.f, 0.f, 0.f, 0.f};
    if (grp == 0) {                        // self-loop counted once
        float w = __expf(lrelu(g_as2[d] + adst));
        den = w;
        uint4 raw = *(const uint4*)(g_h2h + (size_t)d * HID + ch);
        const __half2* hp = (const __half2*)&raw;
#pragma unroll
        for (int i = 0; i < 4; i++) {
            float2 v = __half22float2(hp[i]);
            a[2 * i]     = w * v.x;
            a[2 * i + 1] = w * v.y;
        }
    }

    int beg = g_rowptr[d], end = g_rowptr[d + 1];
#pragma unroll 2
    for (int j = beg + grp; j < end; j += 4) {
        int s = g_col[j];
        float ww = __expf(lrelu(g_as2[s] + adst));
        den += ww;
        uint4 raw = *(const uint4*)(g_h2h + (size_t)s * HID + ch);
        const __half2* hp = (const __half2*)&raw;
#pragma unroll
        for (int i = 0; i < 4; i++) {
            float2 v = __half22float2(hp[i]);
            a[2 * i]     = fmaf(ww, v.x, a[2 * i]);
            a[2 * i + 1] = fmaf(ww, v.y, a[2 * i + 1]);
        }
    }

#pragma unroll
    for (int m = 8; m <= 16; m <<= 1) {
        den += __shfl_xor_sync(0xffffffffu, den, m);
#pragma unroll
        for (int i = 0; i < 8; i++) a[i] += __shfl_xor_sync(0xffffffffu, a[i], m);
    }

    float inv = 1.f / den;
    if (grp == 0) {
#pragma unroll
        for (int i = 0; i < 8; i++) {
            float hv = a[i] * inv + b2[ch + i];
            hv = hv > 0.f ? hv : expm1f(hv);
            sh[wid][ch + i] = hv;
        }
    }
    __syncwarp();

    float acc = bm1[l];
#pragma unroll
    for (int k = 0; k < HID; k++) acc = fmaf(sh[wid][k], Wm1[k * 32 + l], acc);
    float hid = acc > 0.f ? acc : 0.f;

    float p0 = hid * Wm2[l * 2];
    float p1 = hid * Wm2[l * 2 + 1];
#pragma unroll
    for (int s = 16; s >= 1; s >>= 1) {
        p0 += __shfl_xor_sync(0xffffffffu, p0, s);
        p1 += __shfl_xor_sync(0xffffffffu, p1, s);
    }
    if (l == 0) {
        out[d * 2]     = p0 + bm2[0];
        out[d * 2 + 1] = p1 + bm2[1];
    }
}

// ---------------- launch ----------------------------------------------------
extern "C" void kernel_launch(void* const* d_in, const int* in_sizes, int n_in,
                              void* d_out, int out_size) {
    const float* x   = (const float*)d_in[0];
    const int*   ei  = (const int*)  d_in[1];   // [2, E] int32: row0=src, row1=dst
    const float* W1  = (const float*)d_in[2];
    const float* as1 = (const float*)d_in[3];
    const float* ad1 = (const float*)d_in[4];
    const float* b1  = (const float*)d_in[5];
    const float* W2  = (const float*)d_in[6];
    const float* as2 = (const float*)d_in[7];
    const float* ad2 = (const float*)d_in[8];
    const float* b2  = (const float*)d_in[9];
    const float* Wm1 = (const float*)d_in[10];
    const float* bm1 = (const float*)d_in[11];
    const float* Wm2 = (const float*)d_in[12];
    const float* bm2 = (const float*)d_in[13];
    float* out = (float*)d_out;

    const int* src = ei;
    const int* dst = ei + NEDGES;

    cudaFuncSetAttribute(k_gemm1, cudaFuncAttributeMaxDynamicSharedMemorySize, SZ1);
    cudaFuncSetAttribute(k_gemm2, cudaFuncAttributeMaxDynamicSharedMemorySize, SZ2);

    k_gemm1  <<<(NNODES + 63) / 64, 512, SZ1>>>(x, W1, dst, as1, ad1);  // 0 (+hist)
    k_scan1  <<<49, 1024>>>();                                          // 1
    k_scan23 <<<49, 1024>>>();                                          // 2
    k_scatter<<<(NEDGES + 255) / 256, 256>>>(src, dst);                 // 3 <- profiled
    k_agg1   <<<(NNODES + 3) / 4, 128>>>(b1);                           // 4
    k_gemm2  <<<(NNODES + 63) / 64, 512, SZ2>>>(W2, as2, ad2);          // 5
    k_agg2   <<<(NNODES + 3) / 4, 128>>>(b2, Wm1, bm1, Wm2, bm2, out);  // 6
}

// round 16
// speedup vs baseline: 1.0194x; 1.0194x over previous
#include <cuda_runtime.h>
#include <cuda_fp16.h>
#include <mma.h>
#include <math.h>

using namespace nvcuda;

#define NNODES 50000
#define NEDGES 800000
#define INF    128
#define HID    64
#define HEADS  4
#define C1     256   // HEADS*HID
#define NEG    0.2f

// ---------------- scratch (device globals; no runtime allocation) ----------
__device__ __half g_h1h [NNODES * C1];  // layer1 pre-attention features (fp16)
__device__ __half g_h1eh[NNODES * C1];  // layer1 output (post bias+ELU), fp16
__device__ float  g_as1[NNODES * HEADS];
__device__ float  g_ad1[NNODES * HEADS];
__device__ __half g_h2h[NNODES * HID];  // layer2 pre-attention features (fp16)
__device__ float  g_as2[NNODES];
__device__ float  g_ad2[NNODES];
__device__ int    g_deg   [NNODES];
__device__ int    g_rowptr[NNODES + 1];
__device__ int    g_cursor[NNODES];
__device__ int    g_col   [NEDGES];
__device__ int    g_bsum  [64];

__device__ __forceinline__ float lrelu(float v) { return v > 0.f ? v : NEG * v; }

// ---------------- CSR construction (stream s2, overlapped with gemm1) -------
__global__ void k_hist(const int* __restrict__ dst) {
    int i = blockIdx.x * blockDim.x + threadIdx.x;
    if (i < NEDGES) atomicAdd(&g_deg[dst[i]], 1);
}

__global__ void k_scan1() {
    __shared__ int sh[1024];
    int tid = threadIdx.x;
    int i = blockIdx.x * 1024 + tid;
    int v = (i < NNODES) ? g_deg[i] : 0;
    sh[tid] = v;
    __syncthreads();
    for (int s = 1; s < 1024; s <<= 1) {
        int t = (tid >= s) ? sh[tid - s] : 0;
        __syncthreads();
        sh[tid] += t;
        __syncthreads();
    }
    if (i < NNODES) g_rowptr[i] = sh[tid] - v;
    if (tid == 1023) g_bsum[blockIdx.x] = sh[1023];
}

// apply per-block offset, init cursor, zero g_deg for next replay
__global__ void k_scan23() {
    __shared__ int soff;
    int tid = threadIdx.x;
    int bid = blockIdx.x;
    if (tid < 32) {
        int v = 0;
        if (tid < bid && tid < 49) v += g_bsum[tid];
        int t2 = tid + 32;
        if (t2 < bid && t2 < 49) v += g_bsum[t2];
#pragma unroll
        for (int s = 16; s >= 1; s >>= 1) v += __shfl_xor_sync(0xffffffffu, v, s);
        if (tid == 0) soff = v;
    }
    __syncthreads();
    int i = bid * 1024 + tid;
    if (i < NNODES) {
        int r = g_rowptr[i] + soff;
        g_rowptr[i] = r;
        g_cursor[i] = r;
        g_deg[i] = 0;
    }
    if (i == 0) g_rowptr[NNODES] = NEDGES;
}

__global__ void k_scatter(const int* __restrict__ src, const int* __restrict__ dst) {
    int i = blockIdx.x * blockDim.x + threadIdx.x;
    if (i < NEDGES) {
        int p = atomicAdd(&g_cursor[dst[i]], 1);
        g_col[p] = src[i];
    }
}

// ---------------- layer 1 GEMM via wmma: 64 nodes x 256 ch per block --------
// 512 threads = 16 warps as 2m x 8n; warp tile 32 x 32 (2x2 accum frags).
// W1 fp32->fp16 conversion inline in B staging; fused attention dots.
// Single-phase epilogue; attention vectors staged TRANSPOSED (conflict-free).
// smem: mainloop [0,17408) sA | [17408,84992) sB ; epilogue [0,66560) sC
//       [84992,86016) attTs | [86016,87040) attTd
#define SZ1 87040
__global__ void __launch_bounds__(512, 2)
k_gemm1(const float* __restrict__ x, const float* __restrict__ W1,
        const float* __restrict__ att_s, const float* __restrict__ att_d) {
    extern __shared__ __align__(16) char smem[];
    __half* sA = (__half*)smem;
    __half* sB = (__half*)(smem + 17408);
    float*  sC = (float*)smem;                 // aliases sA+sB (dead after mainloop)
    float*  attTs = (float*)(smem + 84992);    // attTs[i*32+q] = att_s[q*8+i]
    float*  attTd = (float*)(smem + 86016);
    int t = threadIdx.x;
    int w = t >> 5;
    int wmh = w & 1, wng = w >> 1;             // m-half 0..1, n-group 0..7
    int m0 = blockIdx.x * 64;

    // stage transposed attention vectors (own region; no aliasing)
    if (t < C1)           attTs[(t & 7) * 32 + (t >> 3)] = att_s[t];
    else if (t < 2 * C1)  { int u = t - C1; attTd[(u & 7) * 32 + (u >> 3)] = att_d[u]; }

    // stage A with fused fp32->fp16: 64 rows x 128 ch
    for (int i = t; i < 1024; i += 512) {
        int r = i >> 4, q = i & 15;
        int n = m0 + r;
        uint4 st = make_uint4(0, 0, 0, 0);
        if (n < NNODES) {
            const float4* xp = (const float4*)(x + (size_t)n * INF + q * 8);
            float4 v0 = xp[0], v1 = xp[1];
            __half2* p = (__half2*)&st;
            p[0] = __floats2half2_rn(v0.x, v0.y);
            p[1] = __floats2half2_rn(v0.z, v0.w);
            p[2] = __floats2half2_rn(v1.x, v1.y);
            p[3] = __floats2half2_rn(v1.z, v1.w);
        }
        *(uint4*)(sA + r * 136 + q * 8) = st;
    }
    // stage B with fused fp32->fp16: all of W1 (128 rows x 256)
    for (int i = t; i < 4096; i += 512) {
        int r = i >> 5, q = i & 31;
        const float4* wp = (const float4*)(W1 + (size_t)r * C1 + q * 8);
        float4 v0 = wp[0], v1 = wp[1];
        uint4 st;
        __half2* p = (__half2*)&st;
        p[0] = __floats2half2_rn(v0.x, v0.y);
        p[1] = __floats2half2_rn(v0.z, v0.w);
        p[2] = __floats2half2_rn(v1.x, v1.y);
        p[3] = __floats2half2_rn(v1.z, v1.w);
        *(uint4*)(sB + r * 264 + q * 8) = st;
    }
    __syncthreads();

    wmma::fragment<wmma::accumulator, 16, 16, 16, float> c[2][2];
#pragma unroll
    for (int i = 0; i < 2; i++)
#pragma unroll
        for (int j = 0; j < 2; j++) wmma::fill_fragment(c[i][j], 0.f);

#pragma unroll
    for (int kk = 0; kk < 8; kk++) {
        wmma::fragment<wmma::matrix_a, 16, 16, 16, __half, wmma::row_major> af[2];
#pragma unroll
        for (int i = 0; i < 2; i++)
            wmma::load_matrix_sync(af[i], sA + (wmh * 2 + i) * 16 * 136 + kk * 16, 136);
#pragma unroll
        for (int j = 0; j < 2; j++) {
            wmma::fragment<wmma::matrix_b, 16, 16, 16, __half, wmma::row_major> bf;
            wmma::load_matrix_sync(bf, sB + kk * 16 * 264 + (wng * 2 + j) * 16, 264);
            wmma::mma_sync(c[0][j], af[0], bf, c[0][j]);
            wmma::mma_sync(c[1][j], af[1], bf, c[1][j]);
        }
    }

    __syncthreads();                 // sA/sB dead; sC live
#pragma unroll
    for (int i = 0; i < 2; i++)
#pragma unroll
        for (int j = 0; j < 2; j++)
            wmma::store_matrix_sync(sC + ((wmh * 2 + i) * 16) * 260 + (wng * 2 + j) * 16,
                                    c[i][j], 260, wmma::mem_row_major);
    __syncthreads();

    // each thread: 4 rows x 8 cols; fp16 store + fused attention dots
    int r0 = t >> 5, q = t & 31, c0 = q * 8;
#pragma unroll
    for (int k = 0; k < 4; k++) {
        int r = r0 + k * 16;
        int n = m0 + r;
        const float* src = sC + r * 260 + c0;
        if (n < NNODES) {
            uint4 st;
            __half2* p = (__half2*)&st;
            p[0] = __floats2half2_rn(src[0], src[1]);
            p[1] = __floats2half2_rn(src[2], src[3]);
            p[2] = __floats2half2_rn(src[4], src[5]);
            p[3] = __floats2half2_rn(src[6], src[7]);
            *(uint4*)(g_h1h + (size_t)n * C1 + c0) = st;
        }
        float ps = 0.f, pd = 0.f;
#pragma unroll
        for (int i = 0; i < 8; i++) {
            float v = src[i];
            ps = fmaf(v, attTs[i * 32 + q], ps);
            pd = fmaf(v, attTd[i * 32 + q], pd);
        }
#pragma unroll
        for (int s = 1; s <= 4; s <<= 1) {
            ps += __shfl_xor_sync(0xffffffffu, ps, s);
            pd += __shfl_xor_sync(0xffffffffu, pd, s);
        }
        if ((q & 7) == 0 && n < NNODES) {
            int h = q >> 3;
            g_as1[n * HEADS + h] = ps;
            g_ad1[n * HEADS + h] = pd;
        }
    }
}

// ---------------- layer 1: warp-per-destination softmax aggregation ---------
// scores |e| <~ 10 so exp() cannot overflow fp32; max-shift unnecessary.
__global__ void k_agg1(const float* __restrict__ b1) {
    int wid = threadIdx.x >> 5, l = threadIdx.x & 31;
    int d = blockIdx.x * 4 + wid;
    if (d >= NNODES) return;
    int h = l >> 3;
    int ch = 8 * l;

    float adst = g_ad1[d * HEADS + h];
    float w = __expf(lrelu(g_as1[d * HEADS + h] + adst));  // self-loop
    float den = w;
    float a[8];
    {
        uint4 raw = *(const uint4*)(g_h1h + (size_t)d * C1 + ch);
        const __half2* hp = (const __half2*)&raw;
#pragma unroll
        for (int i = 0; i < 4; i++) {
            float2 v = __half22float2(hp[i]);
            a[2 * i]     = w * v.x;
            a[2 * i + 1] = w * v.y;
        }
    }

    int beg = g_rowptr[d], end = g_rowptr[d + 1];
#pragma unroll 4
    for (int j = beg; j < end; j++) {
        int s = g_col[j];
        float ww = __expf(lrelu(g_as1[s * HEADS + h] + adst));
        den += ww;
        uint4 raw = *(const uint4*)(g_h1h + (size_t)s * C1 + ch);
        const __half2* hp = (const __half2*)&raw;
#pragma unroll
        for (int i = 0; i < 4; i++) {
            float2 v = __half22float2(hp[i]);
            a[2 * i]     = fmaf(ww, v.x, a[2 * i]);
            a[2 * i + 1] = fmaf(ww, v.y, a[2 * i + 1]);
        }
    }
    float inv = 1.f / den;
    float4 b0 = *(const float4*)(b1 + ch);
    float4 b4 = *(const float4*)(b1 + ch + 4);
    float o[8];
    o[0] = a[0] * inv + b0.x; o[1] = a[1] * inv + b0.y;
    o[2] = a[2] * inv + b0.z; o[3] = a[3] * inv + b0.w;
    o[4] = a[4] * inv + b4.x; o[5] = a[5] * inv + b4.y;
    o[6] = a[6] * inv + b4.z; o[7] = a[7] * inv + b4.w;
#pragma unroll
    for (int i = 0; i < 8; i++) o[i] = o[i] > 0.f ? o[i] : expm1f(o[i]);
    uint4 st;
    __half2* sp = (__half2*)&st;
    sp[0] = __floats2half2_rn(o[0], o[1]);
    sp[1] = __floats2half2_rn(o[2], o[3]);
    sp[2] = __floats2half2_rn(o[4], o[5]);
    sp[3] = __floats2half2_rn(o[6], o[7]);
    *(uint4*)(g_h1eh + (size_t)d * C1 + ch) = st;
}

// ---------------- layer 2 GEMM via wmma: 64 nodes x 64 ch per block ---------
// 512 threads = 16 warps (4m x 4n); warp tile 16 x 16 (1 accum frag).
// W2 fp32->fp16 conversion inline in B staging.
// layout: mainloop [0,33792) sA | [33792,70656) sB
//         epilogue [0,17408) sC | [70656,70912) attTs | [70912,71168) attTd
#define SZ2 71168
__global__ void __launch_bounds__(512, 2)
k_gemm2(const float* __restrict__ W2,
        const float* __restrict__ att_s, const float* __restrict__ att_d) {
    extern __shared__ __align__(16) char smem[];
    __half* sA = (__half*)smem;
    __half* sB = (__half*)(smem + 33792);
    float*  sC = (float*)smem;                 // aliases sA (dead after mainloop)
    float*  attTs = (float*)(smem + 70656);    // attTs[i*32+q] = att_s[q*2+i]
    float*  attTd = (float*)(smem + 70912);
    int t = threadIdx.x;
    int w = t >> 5;
    int wm = w >> 2, wn = w & 3;
    int m0 = blockIdx.x * 64;

    if (t < HID)            attTs[(t & 1) * 32 + (t >> 1)] = att_s[t];
    else if (t < 2 * HID)   { int u = t - HID; attTd[(u & 1) * 32 + (u >> 1)] = att_d[u]; }

    // stage A: 64 rows x 256 fp16
    for (int i = t; i < 2048; i += 512) {
        int r = i >> 5, q = i & 31;
        uint4 v = make_uint4(0, 0, 0, 0);
        if (m0 + r < NNODES) v = *(const uint4*)(g_h1eh + (size_t)(m0 + r) * C1 + q * 8);
        *(uint4*)(sA + r * 264 + q * 8) = v;
    }
    // stage B with fused fp32->fp16: all of W2 (256 rows x 64)
    for (int i = t; i < 2048; i += 512) {
        int r = i >> 3, q = i & 7;
        const float4* wp = (const float4*)(W2 + (size_t)r * HID + q * 8);
        float4 v0 = wp[0], v1 = wp[1];
        uint4 st;
        __half2* p = (__half2*)&st;
        p[0] = __floats2half2_rn(v0.x, v0.y);
        p[1] = __floats2half2_rn(v0.z, v0.w);
        p[2] = __floats2half2_rn(v1.x, v1.y);
        p[3] = __floats2half2_rn(v1.z, v1.w);
        *(uint4*)(sB + r * 72 + q * 8) = st;
    }
    __syncthreads();

    wmma::fragment<wmma::accumulator, 16, 16, 16, float> c;
    wmma::fill_fragment(c, 0.f);

#pragma unroll
    for (int kk = 0; kk < 16; kk++) {
        wmma::fragment<wmma::matrix_a, 16, 16, 16, __half, wmma::row_major> af;
        wmma::load_matrix_sync(af, sA + wm * 16 * 264 + kk * 16, 264);
        wmma::fragment<wmma::matrix_b, 16, 16, 16, __half, wmma::row_major> bf;
        wmma::load_matrix_sync(bf, sB + kk * 16 * 72 + wn * 16, 72);
        wmma::mma_sync(c, af, bf, c);
    }

    __syncthreads();                 // sA/sB dead
    wmma::store_matrix_sync(sC + (wm * 16) * 68 + wn * 16, c, 68, wmma::mem_row_major);
    __syncthreads();

    // each thread: 4 rows x 2 cols
    int r0 = t >> 5, q = t & 31, c0 = q * 2;
#pragma unroll
    for (int k = 0; k < 4; k++) {
        int r = r0 + k * 16;
        int n = m0 + r;
        const float* src = sC + r * 68 + c0;
        if (n < NNODES)
            *(__half2*)(g_h2h + (size_t)n * HID + c0) = __floats2half2_rn(src[0], src[1]);
        float ps = src[0] * attTs[q] + src[1] * attTs[32 + q];
        float pd = src[0] * attTd[q] + src[1] * attTd[32 + q];
#pragma unroll
        for (int s = 1; s <= 16; s <<= 1) {
            ps += __shfl_xor_sync(0xffffffffu, ps, s);
            pd += __shfl_xor_sync(0xffffffffu, pd, s);
        }
        if (q == 0 && n < NNODES) {
            g_as2[n] = ps;
            g_ad2[n] = pd;
        }
    }
}

// ---------------- layer 2 aggregation + bias/ELU + MLP head -----------------
__global__ void k_agg2(const float* __restrict__ b2,
                       const float* __restrict__ Wm1, const float* __restrict__ bm1,
                       const float* __restrict__ Wm2, const float* __restrict__ bm2,
                       float* __restrict__ out) {
    __shared__ float sh[4][HID];
    int wid = threadIdx.x >> 5, l = threadIdx.x & 31;
    int d = blockIdx.x * 4 + wid;
    if (d >= NNODES) return;
    int grp = l >> 3, cl = l & 7;
    int ch = 8 * cl;

    float adst = g_ad2[d];
    float den = 0.f;
    float a[8] = {0.f, 0.f, 0.f, 0.f, 0.f, 0.f, 0.f, 0.f};
    if (grp == 0) {                        // self-loop counted once
        float w = __expf(lrelu(g_as2[d] + adst));
        den = w;
        uint4 raw = *(const uint4*)(g_h2h + (size_t)d * HID + ch);
        const __half2* hp = (const __half2*)&raw;
#pragma unroll
        for (int i = 0; i < 4; i++) {
            float2 v = __half22float2(hp[i]);
            a[2 * i]     = w * v.x;
            a[2 * i + 1] = w * v.y;
        }
    }

    int beg = g_rowptr[d], end = g_rowptr[d + 1];
#pragma unroll 2
    for (int j = beg + grp; j < end; j += 4) {
        int s = g_col[j];
        float ww = __expf(lrelu(g_as2[s] + adst));
        den += ww;
        uint4 raw = *(const uint4*)(g_h2h + (size_t)s * HID + ch);
        const __half2* hp = (const __half2*)&raw;
#pragma unroll
        for (int i = 0; i < 4; i++) {
            float2 v = __half22float2(hp[i]);
            a[2 * i]     = fmaf(ww, v.x, a[2 * i]);
            a[2 * i + 1] = fmaf(ww, v.y, a[2 * i + 1]);
        }
    }

#pragma unroll
    for (int m = 8; m <= 16; m <<= 1) {
        den += __shfl_xor_sync(0xffffffffu, den, m);
#pragma unroll
        for (int i = 0; i < 8; i++) a[i] += __shfl_xor_sync(0xffffffffu, a[i], m);
    }

    float inv = 1.f / den;
    if (grp == 0) {
#pragma unroll
        for (int i = 0; i < 8; i++) {
            float hv = a[i] * inv + b2[ch + i];
            hv = hv > 0.f ? hv : expm1f(hv);
            sh[wid][ch + i] = hv;
        }
    }
    __syncwarp();

    float acc = bm1[l];
#pragma unroll
    for (int k = 0; k < HID; k++) acc = fmaf(sh[wid][k], Wm1[k * 32 + l], acc);
    float hid = acc > 0.f ? acc : 0.f;

    float p0 = hid * Wm2[l * 2];
    float p1 = hid * Wm2[l * 2 + 1];
#pragma unroll
    for (int s = 16; s >= 1; s >>= 1) {
        p0 += __shfl_xor_sync(0xffffffffu, p0, s);
        p1 += __shfl_xor_sync(0xffffffffu, p1, s);
    }
    if (l == 0) {
        out[d * 2]     = p0 + bm2[0];
        out[d * 2 + 1] = p1 + bm2[1];
    }
}

// ---------------- launch: dual-stream overlap (CSR chain || gemm1) ----------
extern "C" void kernel_launch(void* const* d_in, const int* in_sizes, int n_in,
                              void* d_out, int out_size) {
    const float* x   = (const float*)d_in[0];
    const int*   ei  = (const int*)  d_in[1];   // [2, E] int32: row0=src, row1=dst
    const float* W1  = (const float*)d_in[2];
    const float* as1 = (const float*)d_in[3];
    const float* ad1 = (const float*)d_in[4];
    const float* b1  = (const float*)d_in[5];
    const float* W2  = (const float*)d_in[6];
    const float* as2 = (const float*)d_in[7];
    const float* ad2 = (const float*)d_in[8];
    const float* b2  = (const float*)d_in[9];
    const float* Wm1 = (const float*)d_in[10];
    const float* bm1 = (const float*)d_in[11];
    const float* Wm2 = (const float*)d_in[12];
    const float* bm2 = (const float*)d_in[13];
    float* out = (float*)d_out;

    const int* src = ei;
    const int* dst = ei + NEDGES;

    static cudaStream_t s1 = nullptr, s2 = nullptr;
    static cudaEvent_t evFork = nullptr, evJ1 = nullptr, evJ2 = nullptr;
    if (s1 == nullptr) {
        cudaStreamCreateWithFlags(&s1, cudaStreamNonBlocking);
        cudaStreamCreateWithFlags(&s2, cudaStreamNonBlocking);
        cudaEventCreateWithFlags(&evFork, cudaEventDisableTiming);
        cudaEventCreateWithFlags(&evJ1, cudaEventDisableTiming);
        cudaEventCreateWithFlags(&evJ2, cudaEventDisableTiming);
        cudaFuncSetAttribute(k_gemm1, cudaFuncAttributeMaxDynamicSharedMemorySize, SZ1);
        cudaFuncSetAttribute(k_gemm2, cudaFuncAttributeMaxDynamicSharedMemorySize, SZ2);
    }

    // fork from the capture (default) stream
    cudaEventRecord(evFork, 0);
    cudaStreamWaitEvent(s1, evFork, 0);
    cudaStreamWaitEvent(s2, evFork, 0);

    // s2: CSR chain   |   s1: gemm1 (independent)
    k_hist   <<<(NEDGES + 255) / 256, 256, 0, s2>>>(dst);
    k_scan1  <<<49, 1024, 0, s2>>>();
    k_scan23 <<<49, 1024, 0, s2>>>();
    k_gemm1  <<<(NNODES + 63) / 64, 512, SZ1, s1>>>(x, W1, as1, ad1);
    k_scatter<<<(NEDGES + 255) / 256, 256, 0, s2>>>(src, dst);

    // join both branches back into the default stream
    cudaEventRecord(evJ1, s1);
    cudaEventRecord(evJ2, s2);
    cudaStreamWaitEvent(0, evJ1, 0);
    cudaStreamWaitEvent(0, evJ2, 0);

    k_agg1   <<<(NNODES + 3) / 4, 128>>>(b1);
    k_gemm2  <<<(NNODES + 63) / 64, 512, SZ2>>>(W2, as2, ad2);
    k_agg2   <<<(NNODES + 3) / 4, 128>>>(b2, Wm1, bm1, Wm2, bm2, out);
}

// round 17
// speedup vs baseline: 1.0292x; 1.0097x over previous
#include <cuda_runtime.h>
#include <cuda_fp16.h>
#include <mma.h>
#include <math.h>

using namespace nvcuda;

#define NNODES 50000
#define NEDGES 800000
#define INF    128
#define HID    64
#define HEADS  4
#define C1     256   // HEADS*HID
#define NEG    0.2f

// ---------------- scratch (device globals; no runtime allocation) ----------
__device__ __half g_h1h [NNODES * C1];  // layer1 pre-attention features (fp16)
__device__ float  g_as1[NNODES * HEADS];
__device__ float  g_ad1[NNODES * HEADS];
__device__ __half g_h2h[NNODES * HID];  // layer2 pre-attention features (fp16)
__device__ float  g_as2[NNODES];
__device__ float  g_ad2[NNODES];
__device__ int    g_deg   [NNODES];
__device__ int    g_rowptr[NNODES + 1];
__device__ int    g_cursor[NNODES];
__device__ int    g_col   [NEDGES];
__device__ int    g_bsum  [64];

__device__ __forceinline__ float lrelu(float v) { return v > 0.f ? v : NEG * v; }

// ---------------- CSR construction (stream s2, overlapped with gemm1) -------
__global__ void k_hist(const int* __restrict__ dst) {
    int i = blockIdx.x * blockDim.x + threadIdx.x;
    if (i < NEDGES) atomicAdd(&g_deg[dst[i]], 1);
}

__global__ void k_scan1() {
    __shared__ int sh[1024];
    int tid = threadIdx.x;
    int i = blockIdx.x * 1024 + tid;
    int v = (i < NNODES) ? g_deg[i] : 0;
    sh[tid] = v;
    __syncthreads();
    for (int s = 1; s < 1024; s <<= 1) {
        int t = (tid >= s) ? sh[tid - s] : 0;
        __syncthreads();
        sh[tid] += t;
        __syncthreads();
    }
    if (i < NNODES) g_rowptr[i] = sh[tid] - v;
    if (tid == 1023) g_bsum[blockIdx.x] = sh[1023];
}

// apply per-block offset, init cursor, zero g_deg for next replay
__global__ void k_scan23() {
    __shared__ int soff;
    int tid = threadIdx.x;
    int bid = blockIdx.x;
    if (tid < 32) {
        int v = 0;
        if (tid < bid && tid < 49) v += g_bsum[tid];
        int t2 = tid + 32;
        if (t2 < bid && t2 < 49) v += g_bsum[t2];
#pragma unroll
        for (int s = 16; s >= 1; s >>= 1) v += __shfl_xor_sync(0xffffffffu, v, s);
        if (tid == 0) soff = v;
    }
    __syncthreads();
    int i = bid * 1024 + tid;
    if (i < NNODES) {
        int r = g_rowptr[i] + soff;
        g_rowptr[i] = r;
        g_cursor[i] = r;
        g_deg[i] = 0;
    }
    if (i == 0) g_rowptr[NNODES] = NEDGES;
}

__global__ void k_scatter(const int* __restrict__ src, const int* __restrict__ dst) {
    int i = blockIdx.x * blockDim.x + threadIdx.x;
    if (i < NEDGES) {
        int p = atomicAdd(&g_cursor[dst[i]], 1);
        g_col[p] = src[i];
    }
}

// ---------------- layer 1 GEMM via wmma: 64 nodes x 256 ch per block --------
// 512 threads = 16 warps as 2m x 8n; warp tile 32 x 32 (2x2 accum frags).
// W1 fp32->fp16 conversion inline in B staging; fused attention dots.
// smem: mainloop [0,17408) sA | [17408,84992) sB ; epilogue [0,66560) sC
//       [84992,86016) attTs | [86016,87040) attTd
#define SZ1 87040
__global__ void __launch_bounds__(512, 2)
k_gemm1(const float* __restrict__ x, const float* __restrict__ W1,
        const float* __restrict__ att_s, const float* __restrict__ att_d) {
    extern __shared__ __align__(16) char smem[];
    __half* sA = (__half*)smem;
    __half* sB = (__half*)(smem + 17408);
    float*  sC = (float*)smem;                 // aliases sA+sB (dead after mainloop)
    float*  attTs = (float*)(smem + 84992);    // attTs[i*32+q] = att_s[q*8+i]
    float*  attTd = (float*)(smem + 86016);
    int t = threadIdx.x;
    int w = t >> 5;
    int wmh = w & 1, wng = w >> 1;             // m-half 0..1, n-group 0..7
    int m0 = blockIdx.x * 64;

    // stage transposed attention vectors (own region; no aliasing)
    if (t < C1)           attTs[(t & 7) * 32 + (t >> 3)] = att_s[t];
    else if (t < 2 * C1)  { int u = t - C1; attTd[(u & 7) * 32 + (u >> 3)] = att_d[u]; }

    // stage A with fused fp32->fp16: 64 rows x 128 ch
    for (int i = t; i < 1024; i += 512) {
        int r = i >> 4, q = i & 15;
        int n = m0 + r;
        uint4 st = make_uint4(0, 0, 0, 0);
        if (n < NNODES) {
            const float4* xp = (const float4*)(x + (size_t)n * INF + q * 8);
            float4 v0 = xp[0], v1 = xp[1];
            __half2* p = (__half2*)&st;
            p[0] = __floats2half2_rn(v0.x, v0.y);
            p[1] = __floats2half2_rn(v0.z, v0.w);
            p[2] = __floats2half2_rn(v1.x, v1.y);
            p[3] = __floats2half2_rn(v1.z, v1.w);
        }
        *(uint4*)(sA + r * 136 + q * 8) = st;
    }
    // stage B with fused fp32->fp16: all of W1 (128 rows x 256)
    for (int i = t; i < 4096; i += 512) {
        int r = i >> 5, q = i & 31;
        const float4* wp = (const float4*)(W1 + (size_t)r * C1 + q * 8);
        float4 v0 = wp[0], v1 = wp[1];
        uint4 st;
        __half2* p = (__half2*)&st;
        p[0] = __floats2half2_rn(v0.x, v0.y);
        p[1] = __floats2half2_rn(v0.z, v0.w);
        p[2] = __floats2half2_rn(v1.x, v1.y);
        p[3] = __floats2half2_rn(v1.z, v1.w);
        *(uint4*)(sB + r * 264 + q * 8) = st;
    }
    __syncthreads();

    wmma::fragment<wmma::accumulator, 16, 16, 16, float> c[2][2];
#pragma unroll
    for (int i = 0; i < 2; i++)
#pragma unroll
        for (int j = 0; j < 2; j++) wmma::fill_fragment(c[i][j], 0.f);

#pragma unroll
    for (int kk = 0; kk < 8; kk++) {
        wmma::fragment<wmma::matrix_a, 16, 16, 16, __half, wmma::row_major> af[2];
#pragma unroll
        for (int i = 0; i < 2; i++)
            wmma::load_matrix_sync(af[i], sA + (wmh * 2 + i) * 16 * 136 + kk * 16, 136);
#pragma unroll
        for (int j = 0; j < 2; j++) {
            wmma::fragment<wmma::matrix_b, 16, 16, 16, __half, wmma::row_major> bf;
            wmma::load_matrix_sync(bf, sB + kk * 16 * 264 + (wng * 2 + j) * 16, 264);
            wmma::mma_sync(c[0][j], af[0], bf, c[0][j]);
            wmma::mma_sync(c[1][j], af[1], bf, c[1][j]);
        }
    }

    __syncthreads();                 // sA/sB dead; sC live
#pragma unroll
    for (int i = 0; i < 2; i++)
#pragma unroll
        for (int j = 0; j < 2; j++)
            wmma::store_matrix_sync(sC + ((wmh * 2 + i) * 16) * 260 + (wng * 2 + j) * 16,
                                    c[i][j], 260, wmma::mem_row_major);
    __syncthreads();

    // each thread: 4 rows x 8 cols; fp16 store + fused attention dots
    int r0 = t >> 5, q = t & 31, c0 = q * 8;
#pragma unroll
    for (int k = 0; k < 4; k++) {
        int r = r0 + k * 16;
        int n = m0 + r;
        const float* src = sC + r * 260 + c0;
        if (n < NNODES) {
            uint4 st;
            __half2* p = (__half2*)&st;
            p[0] = __floats2half2_rn(src[0], src[1]);
            p[1] = __floats2half2_rn(src[2], src[3]);
            p[2] = __floats2half2_rn(src[4], src[5]);
            p[3] = __floats2half2_rn(src[6], src[7]);
            *(uint4*)(g_h1h + (size_t)n * C1 + c0) = st;
        }
        float ps = 0.f, pd = 0.f;
#pragma unroll
        for (int i = 0; i < 8; i++) {
            float v = src[i];
            ps = fmaf(v, attTs[i * 32 + q], ps);
            pd = fmaf(v, attTd[i * 32 + q], pd);
        }
#pragma unroll
        for (int s = 1; s <= 4; s <<= 1) {
            ps += __shfl_xor_sync(0xffffffffu, ps, s);
            pd += __shfl_xor_sync(0xffffffffu, pd, s);
        }
        if ((q & 7) == 0 && n < NNODES) {
            int h = q >> 3;
            g_as1[n * HEADS + h] = ps;
            g_ad1[n * HEADS + h] = pd;
        }
    }
}

// ---------------- FUSED: layer1 aggregation -> layer2 GEMM + dots ------------
// 512 threads = 16 warps; block owns 64 dests. Each warp aggregates 4 dests
// (softmax gather over incoming edges, bias+ELU) writing fp16 rows directly
// into the GEMM sA tile; then the block runs the W2 wmma GEMM + dots2 epilogue.
// layout: mainloop [0,33792) sA | [33792,70656) sB
//         epilogue [0,17408) sC | [70656,70912) attTs | [70912,71168) attTd
#define SZ2 71168
__global__ void __launch_bounds__(512, 2)
k_agg1gemm2(const float* __restrict__ b1, const float* __restrict__ W2,
            const float* __restrict__ att_s, const float* __restrict__ att_d) {
    extern __shared__ __align__(16) char smem[];
    __half* sA = (__half*)smem;
    __half* sB = (__half*)(smem + 33792);
    float*  sC = (float*)smem;                 // aliases sA (dead after mainloop)
    float*  attTs = (float*)(smem + 70656);    // attTs[i*32+q] = att_s[q*2+i]
    float*  attTd = (float*)(smem + 70912);
    int t = threadIdx.x;
    int w = t >> 5, l = t & 31;
    int m0 = blockIdx.x * 64;

    if (t < HID)            attTs[(t & 1) * 32 + (t >> 1)] = att_s[t];
    else if (t < 2 * HID)   { int u = t - HID; attTd[(u & 1) * 32 + (u >> 1)] = att_d[u]; }

    // stage B first (LDGs in flight while we aggregate): W2 fp32->fp16
    for (int i = t; i < 2048; i += 512) {
        int r = i >> 3, q = i & 7;
        const float4* wp = (const float4*)(W2 + (size_t)r * HID + q * 8);
        float4 v0 = wp[0], v1 = wp[1];
        uint4 st;
        __half2* p = (__half2*)&st;
        p[0] = __floats2half2_rn(v0.x, v0.y);
        p[1] = __floats2half2_rn(v0.z, v0.w);
        p[2] = __floats2half2_rn(v1.x, v1.y);
        p[3] = __floats2half2_rn(v1.z, v1.w);
        *(uint4*)(sB + r * 72 + q * 8) = st;
    }

    // aggregation: warp w handles dests m0 + w*4 + k (k=0..3); lane owns 8 ch
    {
        int h = l >> 3;
        int ch = 8 * l;
        float4 bb0 = *(const float4*)(b1 + ch);
        float4 bb4 = *(const float4*)(b1 + ch + 4);
        for (int k = 0; k < 4; k++) {
            int row = w * 4 + k;
            int d = m0 + row;
            uint4 stz = make_uint4(0, 0, 0, 0);
            if (d >= NNODES) {                 // keep GEMM inputs finite
                *(uint4*)(sA + row * 264 + ch) = stz;
                continue;
            }
            float adst = g_ad1[d * HEADS + h];
            float wgt = __expf(lrelu(g_as1[d * HEADS + h] + adst));  // self-loop
            float den = wgt;
            float a[8];
            {
                uint4 raw = *(const uint4*)(g_h1h + (size_t)d * C1 + ch);
                const __half2* hp = (const __half2*)&raw;
#pragma unroll
                for (int i = 0; i < 4; i++) {
                    float2 v = __half22float2(hp[i]);
                    a[2 * i]     = wgt * v.x;
                    a[2 * i + 1] = wgt * v.y;
                }
            }
            int beg = g_rowptr[d], end = g_rowptr[d + 1];
#pragma unroll 4
            for (int j = beg; j < end; j++) {
                int s = g_col[j];
                float ww = __expf(lrelu(g_as1[s * HEADS + h] + adst));
                den += ww;
                uint4 raw = *(const uint4*)(g_h1h + (size_t)s * C1 + ch);
                const __half2* hp = (const __half2*)&raw;
#pragma unroll
                for (int i = 0; i < 4; i++) {
                    float2 v = __half22float2(hp[i]);
                    a[2 * i]     = fmaf(ww, v.x, a[2 * i]);
                    a[2 * i + 1] = fmaf(ww, v.y, a[2 * i + 1]);
                }
            }
            float inv = 1.f / den;
            float o[8];
            o[0] = a[0] * inv + bb0.x; o[1] = a[1] * inv + bb0.y;
            o[2] = a[2] * inv + bb0.z; o[3] = a[3] * inv + bb0.w;
            o[4] = a[4] * inv + bb4.x; o[5] = a[5] * inv + bb4.y;
            o[6] = a[6] * inv + bb4.z; o[7] = a[7] * inv + bb4.w;
#pragma unroll
            for (int i = 0; i < 8; i++) o[i] = o[i] > 0.f ? o[i] : expm1f(o[i]);  // ELU
            uint4 st;
            __half2* sp = (__half2*)&st;
            sp[0] = __floats2half2_rn(o[0], o[1]);
            sp[1] = __floats2half2_rn(o[2], o[3]);
            sp[2] = __floats2half2_rn(o[4], o[5]);
            sp[3] = __floats2half2_rn(o[6], o[7]);
            *(uint4*)(sA + row * 264 + ch) = st;   // straight into the GEMM A tile
        }
    }
    __syncthreads();

    // GEMM: 16 warps (4m x 4n); warp tile 16 x 16
    int wm = w >> 2, wn = w & 3;
    wmma::fragment<wmma::accumulator, 16, 16, 16, float> c;
    wmma::fill_fragment(c, 0.f);
#pragma unroll
    for (int kk = 0; kk < 16; kk++) {
        wmma::fragment<wmma::matrix_a, 16, 16, 16, __half, wmma::row_major> af;
        wmma::load_matrix_sync(af, sA + wm * 16 * 264 + kk * 16, 264);
        wmma::fragment<wmma::matrix_b, 16, 16, 16, __half, wmma::row_major> bf;
        wmma::load_matrix_sync(bf, sB + kk * 16 * 72 + wn * 16, 72);
        wmma::mma_sync(c, af, bf, c);
    }

    __syncthreads();                 // sA/sB dead
    wmma::store_matrix_sync(sC + (wm * 16) * 68 + wn * 16, c, 68, wmma::mem_row_major);
    __syncthreads();

    // each thread: 4 rows x 2 cols; h2h fp16 store + dots2
    int r0 = t >> 5, q = t & 31, c0 = q * 2;
#pragma unroll
    for (int k = 0; k < 4; k++) {
        int r = r0 + k * 16;
        int n = m0 + r;
        const float* src = sC + r * 68 + c0;
        if (n < NNODES)
            *(__half2*)(g_h2h + (size_t)n * HID + c0) = __floats2half2_rn(src[0], src[1]);
        float ps = src[0] * attTs[q] + src[1] * attTs[32 + q];
        float pd = src[0] * attTd[q] + src[1] * attTd[32 + q];
#pragma unroll
        for (int s = 1; s <= 16; s <<= 1) {
            ps += __shfl_xor_sync(0xffffffffu, ps, s);
            pd += __shfl_xor_sync(0xffffffffu, pd, s);
        }
        if (q == 0 && n < NNODES) {
            g_as2[n] = ps;
            g_ad2[n] = pd;
        }
    }
}

// ---------------- layer 2 aggregation + bias/ELU + MLP head -----------------
__global__ void k_agg2(const float* __restrict__ b2,
                       const float* __restrict__ Wm1, const float* __restrict__ bm1,
                       const float* __restrict__ Wm2, const float* __restrict__ bm2,
                       float* __restrict__ out) {
    __shared__ float sh[4][HID];
    int wid = threadIdx.x >> 5, l = threadIdx.x & 31;
    int d = blockIdx.x * 4 + wid;
    if (d >= NNODES) return;
    int grp = l >> 3, cl = l & 7;
    int ch = 8 * cl;

    float adst = g_ad2[d];
    float den = 0.f;
    float a[8] = {0.f, 0.f, 0.f, 0.f, 0.f, 0.f, 0.f, 0.f};
    if (grp == 0) {                        // self-loop counted once
        float w = __expf(lrelu(g_as2[d] + adst));
        den = w;
        uint4 raw = *(const uint4*)(g_h2h + (size_t)d * HID + ch);
        const __half2* hp = (const __half2*)&raw;
#pragma unroll
        for (int i = 0; i < 4; i++) {
            float2 v = __half22float2(hp[i]);
            a[2 * i]     = w * v.x;
            a[2 * i + 1] = w * v.y;
        }
    }

    int beg = g_rowptr[d], end = g_rowptr[d + 1];
#pragma unroll 2
    for (int j = beg + grp; j < end; j += 4) {
        int s = g_col[j];
        float ww = __expf(lrelu(g_as2[s] + adst));
        den += ww;
        uint4 raw = *(const uint4*)(g_h2h + (size_t)s * HID + ch);
        const __half2* hp = (const __half2*)&raw;
#pragma unroll
        for (int i = 0; i < 4; i++) {
            float2 v = __half22float2(hp[i]);
            a[2 * i]     = fmaf(ww, v.x, a[2 * i]);
            a[2 * i + 1] = fmaf(ww, v.y, a[2 * i + 1]);
        }
    }

#pragma unroll
    for (int m = 8; m <= 16; m <<= 1) {
        den += __shfl_xor_sync(0xffffffffu, den, m);
#pragma unroll
        for (int i = 0; i < 8; i++) a[i] += __shfl_xor_sync(0xffffffffu, a[i], m);
    }

    float inv = 1.f / den;
    if (grp == 0) {
#pragma unroll
        for (int i = 0; i < 8; i++) {
            float hv = a[i] * inv + b2[ch + i];
            hv = hv > 0.f ? hv : expm1f(hv);
            sh[wid][ch + i] = hv;
        }
    }
    __syncwarp();

    float acc = bm1[l];
#pragma unroll
    for (int k = 0; k < HID; k++) acc = fmaf(sh[wid][k], Wm1[k * 32 + l], acc);
    float hid = acc > 0.f ? acc : 0.f;

    float p0 = hid * Wm2[l * 2];
    float p1 = hid * Wm2[l * 2 + 1];
#pragma unroll
    for (int s = 16; s >= 1; s >>= 1) {
        p0 += __shfl_xor_sync(0xffffffffu, p0, s);
        p1 += __shfl_xor_sync(0xffffffffu, p1, s);
    }
    if (l == 0) {
        out[d * 2]     = p0 + bm2[0];
        out[d * 2 + 1] = p1 + bm2[1];
    }
}

// ---------------- launch: dual-stream overlap (CSR chain || gemm1) ----------
extern "C" void kernel_launch(void* const* d_in, const int* in_sizes, int n_in,
                              void* d_out, int out_size) {
    const float* x   = (const float*)d_in[0];
    const int*   ei  = (const int*)  d_in[1];   // [2, E] int32: row0=src, row1=dst
    const float* W1  = (const float*)d_in[2];
    const float* as1 = (const float*)d_in[3];
    const float* ad1 = (const float*)d_in[4];
    const float* b1  = (const float*)d_in[5];
    const float* W2  = (const float*)d_in[6];
    const float* as2 = (const float*)d_in[7];
    const float* ad2 = (const float*)d_in[8];
    const float* b2  = (const float*)d_in[9];
    const float* Wm1 = (const float*)d_in[10];
    const float* bm1 = (const float*)d_in[11];
    const float* Wm2 = (const float*)d_in[12];
    const float* bm2 = (const float*)d_in[13];
    float* out = (float*)d_out;

    const int* src = ei;
    const int* dst = ei + NEDGES;

    static cudaStream_t s1 = nullptr, s2 = nullptr;
    static cudaEvent_t evFork = nullptr, evJ1 = nullptr, evJ2 = nullptr;
    if (s1 == nullptr) {
        cudaStreamCreateWithFlags(&s1, cudaStreamNonBlocking);
        cudaStreamCreateWithFlags(&s2, cudaStreamNonBlocking);
        cudaEventCreateWithFlags(&evFork, cudaEventDisableTiming);
        cudaEventCreateWithFlags(&evJ1, cudaEventDisableTiming);
        cudaEventCreateWithFlags(&evJ2, cudaEventDisableTiming);
        cudaFuncSetAttribute(k_gemm1, cudaFuncAttributeMaxDynamicSharedMemorySize, SZ1);
        cudaFuncSetAttribute(k_agg1gemm2, cudaFuncAttributeMaxDynamicSharedMemorySize, SZ2);
    }

    // fork from the capture (default) stream
    cudaEventRecord(evFork, 0);
    cudaStreamWaitEvent(s1, evFork, 0);
    cudaStreamWaitEvent(s2, evFork, 0);

    // s2: CSR chain   |   s1: gemm1 (independent)
    k_hist   <<<(NEDGES + 255) / 256, 256, 0, s2>>>(dst);
    k_scan1  <<<49, 1024, 0, s2>>>();
    k_scan23 <<<49, 1024, 0, s2>>>();
    k_gemm1  <<<(NNODES + 63) / 64, 512, SZ1, s1>>>(x, W1, as1, ad1);
    k_scatter<<<(NEDGES + 255) / 256, 256, 0, s2>>>(src, dst);

    // join both branches back into the default stream
    cudaEventRecord(evJ1, s1);
    cudaEventRecord(evJ2, s2);
    cudaStreamWaitEvent(0, evJ1, 0);
    cudaStreamWaitEvent(0, evJ2, 0);

    k_agg1gemm2<<<(NNODES + 63) / 64, 512, SZ2>>>(b1, W2, as2, ad2);
    k_agg2     <<<(NNODES + 3) / 4, 128>>>(b2, Wm1, bm1, Wm2, bm2, out);
}